// round 6
// baseline (speedup 1.0000x reference)
#include <cuda_runtime.h>
#include <math.h>
#include <stdint.h>

#define BH    32
#define SEQ   2048
#define DIM   1024
#define NH    16
#define HDIM  64
#define MROWS 4096

// ---------------- device scratch (3 int8 planes per tensor) ----------------
__device__ int8_t g_x1[MROWS * DIM], g_x2[MROWS * DIM], g_x3[MROWS * DIM];
__device__ int8_t g_Wq1[DIM * DIM], g_Wq2[DIM * DIM], g_Wq3[DIM * DIM];
__device__ int8_t g_Wk1[DIM * DIM], g_Wk2[DIM * DIM], g_Wk3[DIM * DIM];
__device__ int8_t g_Wv1[DIM * DIM], g_Wv2[DIM * DIM], g_Wv3[DIM * DIM];
__device__ int8_t g_Wo1[DIM * DIM], g_Wo2[DIM * DIM], g_Wo3[DIM * DIM];
__device__ int8_t g_Q1[BH * SEQ * HDIM], g_Q2[BH * SEQ * HDIM], g_Q3[BH * SEQ * HDIM];
__device__ int8_t g_K1[BH * SEQ * HDIM], g_K2[BH * SEQ * HDIM], g_K3[BH * SEQ * HDIM];
__device__ int8_t g_V1[BH * HDIM * SEQ], g_V2[BH * HDIM * SEQ], g_V3[BH * HDIM * SEQ]; // V^T
__device__ float  g_S[(size_t)BH * SEQ * SEQ];
__device__ int8_t g_P1[(size_t)BH * SEQ * SEQ], g_P2[(size_t)BH * SEQ * SEQ],
                  g_P3[(size_t)BH * SEQ * SEQ];
__device__ float  g_Pscale[BH * SEQ];
__device__ int8_t g_A1[MROWS * DIM], g_A2[MROWS * DIM], g_A3[MROWS * DIM];

// ---------------- helpers ----------------
__device__ __forceinline__ uint32_t smem_u32(const void* p) {
    uint32_t a;
    asm("{ .reg .u64 t; cvta.to.shared.u64 t, %1; cvt.u32.u64 %0, t; }" : "=r"(a) : "l"(p));
    return a;
}
__device__ __forceinline__ void cp16(uint32_t s, const void* g) {
    asm volatile("cp.async.cg.shared.global [%0], [%1], 16;" :: "r"(s), "l"(g));
}
__device__ __forceinline__ void mma_s8(int* d, const uint32_t* a, const uint32_t* b) {
    asm volatile(
        "mma.sync.aligned.m16n8k32.row.col.s32.s8.s8.s32 "
        "{%0,%1,%2,%3}, {%4,%5,%6,%7}, {%8,%9}, {%0,%1,%2,%3};"
        : "+r"(d[0]), "+r"(d[1]), "+r"(d[2]), "+r"(d[3])
        : "r"(a[0]), "r"(a[1]), "r"(a[2]), "r"(a[3]), "r"(b[0]), "r"(b[1]));
}
// 3-level int8 quantization of u (safe for |u| < ~1.98): u ≈ r1/64 + r2/8192 + r3/2^20
__device__ __forceinline__ void quant3(float u, int8_t& o1, int8_t& o2, int8_t& o3) {
    float f1 = rintf(u * 64.f);
    f1 = fminf(127.f, fmaxf(-127.f, f1));
    float u1 = u * 64.f - f1;
    float f2 = rintf(u1 * 128.f);
    f2 = fminf(127.f, fmaxf(-127.f, f2));
    float u2 = u1 * 128.f - f2;
    float f3 = fminf(127.f, fmaxf(-127.f, rintf(u2 * 128.f)));
    o1 = (int8_t)(int)f1;
    o2 = (int8_t)(int)f2;
    o3 = (int8_t)(int)f3;
}

// ---------------- conversion kernels ----------------
__global__ __launch_bounds__(256) void qx_kernel(const float* __restrict__ in,
                                                 int8_t* __restrict__ p1,
                                                 int8_t* __restrict__ p2,
                                                 int8_t* __restrict__ p3,
                                                 int n, float qmul) {
    int i = blockIdx.x * 256 + threadIdx.x;
    if (i < n) quant3(in[i] * qmul, p1[i], p2[i], p3[i]);
}

// W[k][n] -> planes [n][k]
__global__ __launch_bounds__(256) void qwT_kernel(const float* __restrict__ W,
                                                  int8_t* __restrict__ p1,
                                                  int8_t* __restrict__ p2,
                                                  int8_t* __restrict__ p3) {
    __shared__ float t[32][33];
    int n0 = blockIdx.x * 32, k0 = blockIdx.y * 32;
    int tx = threadIdx.x & 31, ty = threadIdx.x >> 5;
#pragma unroll
    for (int r = ty; r < 32; r += 8)
        t[r][tx] = W[(size_t)(k0 + r) * DIM + n0 + tx];
    __syncthreads();
#pragma unroll
    for (int r = ty; r < 32; r += 8) {
        size_t idx = (size_t)(n0 + r) * DIM + k0 + tx;
        quant3(t[tx][r] * 32.f, p1[idx], p2[idx], p3[idx]);
    }
}

// ---------------- int8 3-plane GEMM (Ozaki split, 6 IMMA per k32) ----------------
// C = cs * (D1 + D2/128 + D3/16384); modes:
// 0 head-split quant [bh][s][hd], 1 transposed quant [bh][hd][s],
// 2 fp32 out + bias, 3 fp32 scores (batched), 4 merged-head quant with row scale
__global__ __launch_bounds__(256, 1) void gemm_s8(
    const int8_t* __restrict__ A1p, const int8_t* __restrict__ A2p,
    const int8_t* __restrict__ A3p, long strideA, long bStrideA,
    const int8_t* __restrict__ B1p, const int8_t* __restrict__ B2p,
    const int8_t* __restrict__ B3p, long strideB, long bStrideB,
    const float* __restrict__ bias, float cs, float outscale, float qmul,
    int Ktot, int mode,
    int8_t* __restrict__ o1, int8_t* __restrict__ o2, int8_t* __restrict__ o3,
    float* __restrict__ outF, const float* __restrict__ rowscale)
{
    extern __shared__ char smem[];
    constexpr int ROWB = 80;                  // 64 B data + 16 B pad
    constexpr int OFF_A1 = 0;
    constexpr int OFF_A2 = 128 * ROWB;
    constexpr int OFF_A3 = 2 * 128 * ROWB;
    constexpr int OFF_B1 = 3 * 128 * ROWB;
    constexpr int OFF_B2 = OFF_B1 + 64 * ROWB;
    constexpr int OFF_B3 = OFF_B1 + 2 * 64 * ROWB;
    constexpr int STAGE = 3 * 128 * ROWB + 3 * 64 * ROWB;   // 46080

    const int tid = threadIdx.x;
    const int w = tid >> 5, lane = tid & 31;
    const int g = lane >> 2, t = lane & 3;
    const int wm = w & 3, wn = w >> 2;        // 4 x 2 warps, warp tile 32x32
    const int z = blockIdx.z;
    A1p += (size_t)z * bStrideA;  A2p += (size_t)z * bStrideA;  A3p += (size_t)z * bStrideA;
    B1p += (size_t)z * bStrideB;  B2p += (size_t)z * bStrideB;  B3p += (size_t)z * bStrideB;

    const int m0 = blockIdx.y * 128, n0 = blockIdx.x * 64;
    const int nst = Ktot >> 6;
    const uint32_t sb = smem_u32(smem);

    const int aOff = (wm * 32 + g) * ROWB + t * 4;
    const int bOff = (wn * 32 + g) * ROWB + t * 4;

    int D1[2][4][4], D2[2][4][4], D3[2][4][4];
#pragma unroll
    for (int i = 0; i < 2; i++)
#pragma unroll
        for (int j = 0; j < 4; j++)
#pragma unroll
            for (int k = 0; k < 4; k++) { D1[i][j][k] = 0; D2[i][j][k] = 0; D3[i][j][k] = 0; }

    auto stage_load = [&](int buf, int c) {
        const int k0 = c << 6;
        const uint32_t so = sb + buf * STAGE;
#pragma unroll
        for (int i = tid; i < 512; i += 256) {       // A: 128 rows x 4 segs of 16B
            int r = i >> 2, cc = i & 3;
            uint32_t off = r * ROWB + cc * 16;
            const size_t gofs = (size_t)(m0 + r) * strideA + k0 + cc * 16;
            cp16(so + OFF_A1 + off, A1p + gofs);
            cp16(so + OFF_A2 + off, A2p + gofs);
            cp16(so + OFF_A3 + off, A3p + gofs);
        }
        {
            int i = tid;
            if (i < 256) {                           // B: 64 rows x 4 segs
                int r = i >> 2, cc = i & 3;
                uint32_t off = r * ROWB + cc * 16;
                const size_t gofs = (size_t)(n0 + r) * strideB + k0 + cc * 16;
                cp16(so + OFF_B1 + off, B1p + gofs);
                cp16(so + OFF_B2 + off, B2p + gofs);
                cp16(so + OFF_B3 + off, B3p + gofs);
            }
        }
        asm volatile("cp.async.commit_group;");
    };

    stage_load(0, 0);
    for (int c = 0; c < nst; c++) {
        const int buf = c & 1;
        if (c + 1 < nst) {
            stage_load(buf ^ 1, c + 1);
            asm volatile("cp.async.wait_group 1;");
        } else {
            asm volatile("cp.async.wait_group 0;");
        }
        __syncthreads();

#pragma unroll
        for (int ks = 0; ks < 2; ks++) {
            const int ko = buf * STAGE + ks * 32;
            uint32_t a1f[2][4], a2f[2][4], a3f[2][4];
            uint32_t b1f[4][2], b2f[4][2], b3f[4][2];
#pragma unroll
            for (int mt = 0; mt < 2; mt++) {
                const int p = ko + aOff + mt * 16 * ROWB;
                a1f[mt][0] = *(const uint32_t*)(smem + OFF_A1 + p);
                a1f[mt][1] = *(const uint32_t*)(smem + OFF_A1 + p + 8 * ROWB);
                a1f[mt][2] = *(const uint32_t*)(smem + OFF_A1 + p + 16);
                a1f[mt][3] = *(const uint32_t*)(smem + OFF_A1 + p + 8 * ROWB + 16);
                a2f[mt][0] = *(const uint32_t*)(smem + OFF_A2 + p);
                a2f[mt][1] = *(const uint32_t*)(smem + OFF_A2 + p + 8 * ROWB);
                a2f[mt][2] = *(const uint32_t*)(smem + OFF_A2 + p + 16);
                a2f[mt][3] = *(const uint32_t*)(smem + OFF_A2 + p + 8 * ROWB + 16);
                a3f[mt][0] = *(const uint32_t*)(smem + OFF_A3 + p);
                a3f[mt][1] = *(const uint32_t*)(smem + OFF_A3 + p + 8 * ROWB);
                a3f[mt][2] = *(const uint32_t*)(smem + OFF_A3 + p + 16);
                a3f[mt][3] = *(const uint32_t*)(smem + OFF_A3 + p + 8 * ROWB + 16);
            }
#pragma unroll
            for (int nt = 0; nt < 4; nt++) {
                const int p = ko + bOff + nt * 8 * ROWB;
                b1f[nt][0] = *(const uint32_t*)(smem + OFF_B1 + p);
                b1f[nt][1] = *(const uint32_t*)(smem + OFF_B1 + p + 16);
                b2f[nt][0] = *(const uint32_t*)(smem + OFF_B2 + p);
                b2f[nt][1] = *(const uint32_t*)(smem + OFF_B2 + p + 16);
                b3f[nt][0] = *(const uint32_t*)(smem + OFF_B3 + p);
                b3f[nt][1] = *(const uint32_t*)(smem + OFF_B3 + p + 16);
            }
#pragma unroll
            for (int mt = 0; mt < 2; mt++)
#pragma unroll
                for (int nt = 0; nt < 4; nt++) {
                    mma_s8(D1[mt][nt], a1f[mt], b1f[nt]);
                    mma_s8(D2[mt][nt], a1f[mt], b2f[nt]);
                    mma_s8(D2[mt][nt], a2f[mt], b1f[nt]);
                    mma_s8(D3[mt][nt], a1f[mt], b3f[nt]);
                    mma_s8(D3[mt][nt], a2f[mt], b2f[nt]);
                    mma_s8(D3[mt][nt], a3f[mt], b1f[nt]);
                }
        }
        __syncthreads();
    }

    // ---------------- epilogue ----------------
#pragma unroll
    for (int mt = 0; mt < 2; mt++)
#pragma unroll
        for (int nt = 0; nt < 4; nt++)
#pragma unroll
            for (int p = 0; p < 2; p++) {
                const int row = m0 + wm * 32 + mt * 16 + g + 8 * p;
                const int col = n0 + wn * 32 + nt * 8 + 2 * t;
#pragma unroll
                for (int e = 0; e < 2; e++) {
                    const int idx = 2 * p + e;
                    float dq = (float)D1[mt][nt][idx]
                             + (float)D2[mt][nt][idx] * 0.0078125f
                             + (float)D3[mt][nt][idx] * 6.103515625e-5f;
                    const int cc = col + e;
                    if (mode == 0 || mode == 1) {
                        float v = (dq * cs + bias[cc]) * outscale;
                        int b = row >> 11, sq = row & (SEQ - 1);
                        int h = cc >> 6, hd = cc & (HDIM - 1);
                        size_t oi = (mode == 0)
                            ? ((((size_t)b * NH + h) * SEQ + sq) * HDIM + hd)
                            : ((((size_t)b * NH + h) * HDIM + hd) * SEQ + sq);
                        quant3(v * qmul, o1[oi], o2[oi], o3[oi]);
                    } else if (mode == 2) {
                        outF[(size_t)row * DIM + cc] = dq * cs + bias[cc];
                    } else if (mode == 3) {
                        outF[(size_t)z * SEQ * SEQ + (size_t)row * SEQ + cc] = dq * cs;
                    } else {  // mode 4
                        float v = dq * cs * rowscale[(size_t)z * SEQ + row];
                        int b = z >> 4, h = z & (NH - 1);
                        size_t oi = ((size_t)b * SEQ + row) * DIM + h * HDIM + cc;
                        quant3(v * qmul, o1[oi], o2[oi], o3[oi]);
                    }
                }
            }
}

// ---------------- softmax: fp32 scores -> int8 planes of exp(s-max), row scale = 1/sum
__global__ __launch_bounds__(256) void softmax_kernel() {
    const size_t rb = (size_t)blockIdx.x * SEQ;
    const float* p = g_S + rb;
    int tid = threadIdx.x, wid = tid >> 5, lid = tid & 31;
    __shared__ float sred[8];

    float v[8];
    float mx = -1e30f;
#pragma unroll
    for (int i = 0; i < 8; i++) { v[i] = p[tid + i * 256]; mx = fmaxf(mx, v[i]); }
#pragma unroll
    for (int o = 16; o > 0; o >>= 1) mx = fmaxf(mx, __shfl_xor_sync(0xffffffffu, mx, o));
    if (lid == 0) sred[wid] = mx;
    __syncthreads();
    if (wid == 0) {
        float t2 = sred[lid & 7];
#pragma unroll
        for (int o = 4; o > 0; o >>= 1) t2 = fmaxf(t2, __shfl_xor_sync(0xffffffffu, t2, o));
        if (lid == 0) sred[0] = t2;
    }
    __syncthreads();
    mx = sred[0];
    __syncthreads();
    float sum = 0.f;
#pragma unroll
    for (int i = 0; i < 8; i++) { v[i] = __expf(v[i] - mx); sum += v[i]; }
#pragma unroll
    for (int o = 16; o > 0; o >>= 1) sum += __shfl_xor_sync(0xffffffffu, sum, o);
    if (lid == 0) sred[wid] = sum;
    __syncthreads();
    if (wid == 0) {
        float t2 = sred[lid & 7];
#pragma unroll
        for (int o = 4; o > 0; o >>= 1) t2 += __shfl_xor_sync(0xffffffffu, t2, o);
        if (lid == 0) sred[0] = t2;
    }
    __syncthreads();
#pragma unroll
    for (int i = 0; i < 8; i++) {
        size_t oi = rb + tid + i * 256;
        quant3(v[i], g_P1[oi], g_P2[oi], g_P3[oi]);
    }
    if (tid == 0) g_Pscale[blockIdx.x] = 1.0f / sred[0];
}

// ---------------- host ----------------
static void* sym(const void* s) { void* p; cudaGetSymbolAddress(&p, s); return p; }

extern "C" void kernel_launch(void* const* d_in, const int* in_sizes, int n_in,
                              void* d_out, int out_size)
{
    const float* x  = (const float*)d_in[0];
    const float* Wq = (const float*)d_in[1];
    const float* bq = (const float*)d_in[2];
    const float* Wk = (const float*)d_in[3];
    const float* bk = (const float*)d_in[4];
    const float* Wv = (const float*)d_in[5];
    const float* bv = (const float*)d_in[6];
    const float* Wo = (const float*)d_in[7];
    const float* bo = (const float*)d_in[8];
    float* out = (float*)d_out;

    constexpr int SMEM = 2 * (3 * 128 * 80 + 3 * 64 * 80);  // 92160
    cudaFuncSetAttribute(gemm_s8, cudaFuncAttributeMaxDynamicSharedMemorySize, SMEM);

    int8_t *x1 = (int8_t*)sym(g_x1), *x2 = (int8_t*)sym(g_x2), *x3 = (int8_t*)sym(g_x3);
    int8_t *wq1 = (int8_t*)sym(g_Wq1), *wq2 = (int8_t*)sym(g_Wq2), *wq3 = (int8_t*)sym(g_Wq3);
    int8_t *wk1 = (int8_t*)sym(g_Wk1), *wk2 = (int8_t*)sym(g_Wk2), *wk3 = (int8_t*)sym(g_Wk3);
    int8_t *wv1 = (int8_t*)sym(g_Wv1), *wv2 = (int8_t*)sym(g_Wv2), *wv3 = (int8_t*)sym(g_Wv3);
    int8_t *wo1 = (int8_t*)sym(g_Wo1), *wo2 = (int8_t*)sym(g_Wo2), *wo3 = (int8_t*)sym(g_Wo3);
    int8_t *q1 = (int8_t*)sym(g_Q1), *q2 = (int8_t*)sym(g_Q2), *q3 = (int8_t*)sym(g_Q3);
    int8_t *k1 = (int8_t*)sym(g_K1), *k2 = (int8_t*)sym(g_K2), *k3 = (int8_t*)sym(g_K3);
    int8_t *v1 = (int8_t*)sym(g_V1), *v2 = (int8_t*)sym(g_V2), *v3 = (int8_t*)sym(g_V3);
    int8_t *p1 = (int8_t*)sym(g_P1), *p2 = (int8_t*)sym(g_P2), *p3 = (int8_t*)sym(g_P3);
    int8_t *a1 = (int8_t*)sym(g_A1), *a2 = (int8_t*)sym(g_A2), *a3 = (int8_t*)sym(g_A3);
    float *Sf = (float*)sym(g_S), *pscale = (float*)sym(g_Pscale);

    // quantize inputs: S_x = 4 (qmul 0.25), W scale 1/32 (qmul 32)
    qx_kernel<<<(MROWS * DIM + 255) / 256, 256>>>(x, x1, x2, x3, MROWS * DIM, 0.25f);
    dim3 wg(DIM / 32, DIM / 32);
    qwT_kernel<<<wg, 256>>>(Wq, wq1, wq2, wq3);
    qwT_kernel<<<wg, 256>>>(Wk, wk1, wk2, wk3);
    qwT_kernel<<<wg, 256>>>(Wv, wv1, wv2, wv3);
    qwT_kernel<<<wg, 256>>>(Wo, wo1, wo2, wo3);

    dim3 blk(256);
    dim3 gproj(DIM / 64, MROWS / 128, 1);   // 16 x 32

    const float csProj = 4.f * (1.f / 32.f) / 4096.f;   // S_x * S_W / 4096

    // Q: out scaled by 0.125, quantized with S_Q = 1 (qmul 1)
    gemm_s8<<<gproj, blk, SMEM>>>(x1, x2, x3, DIM, 0, wq1, wq2, wq3, DIM, 0,
        bq, csProj, 0.125f, 1.0f, DIM, 0, q1, q2, q3, nullptr, nullptr);
    // K: S_K = 4 (qmul 0.25)
    gemm_s8<<<gproj, blk, SMEM>>>(x1, x2, x3, DIM, 0, wk1, wk2, wk3, DIM, 0,
        bk, csProj, 1.0f, 0.25f, DIM, 0, k1, k2, k3, nullptr, nullptr);
    // V transposed: S_V = 4
    gemm_s8<<<gproj, blk, SMEM>>>(x1, x2, x3, DIM, 0, wv1, wv2, wv3, DIM, 0,
        bv, csProj, 1.0f, 0.25f, DIM, 1, v1, v2, v3, nullptr, nullptr);

    // scores = Qs @ K^T: cs = S_Q * S_K / 4096 = 4/4096
    gemm_s8<<<dim3(SEQ / 64, SEQ / 128, BH), blk, SMEM>>>(
        q1, q2, q3, HDIM, (long)SEQ * HDIM, k1, k2, k3, HDIM, (long)SEQ * HDIM,
        nullptr, 4.f / 4096.f, 1.f, 1.f, HDIM, 3, nullptr, nullptr, nullptr, Sf, nullptr);

    softmax_kernel<<<BH * SEQ, 256>>>();

    // attnV: cs = 1 * S_V / 4096, per-row P scale; attn quantized S = 2 (qmul 0.5)
    gemm_s8<<<dim3(1, SEQ / 128, BH), blk, SMEM>>>(
        p1, p2, p3, SEQ, (long)SEQ * SEQ, v1, v2, v3, SEQ, (long)HDIM * SEQ,
        nullptr, 4.f / 4096.f, 1.f, 0.5f, SEQ, 4, a1, a2, a3, nullptr, pscale);

    // out projection: cs = S_attn * S_Wo / 4096 = 2/32/4096
    gemm_s8<<<gproj, blk, SMEM>>>(a1, a2, a3, DIM, 0, wo1, wo2, wo3, DIM, 0,
        bo, 2.f / 32.f / 4096.f, 1.f, 1.f, DIM, 2, nullptr, nullptr, nullptr, out, nullptr);
}

// round 7
// speedup vs baseline: 3.3086x; 3.3086x over previous
#include <cuda_runtime.h>
#include <cuda_bf16.h>
#include <math.h>
#include <stdint.h>

#define BH    32
#define SEQ   2048
#define DIM   1024
#define NH    16
#define HDIM  64
#define MROWS 4096

// ---------------- device scratch ----------------
__device__ __nv_bfloat16 g_xh[MROWS * DIM], g_xl[MROWS * DIM];
__device__ __nv_bfloat16 g_Wqh[DIM * DIM], g_Wql[DIM * DIM];
__device__ __nv_bfloat16 g_Wkh[DIM * DIM], g_Wkl[DIM * DIM];
__device__ __nv_bfloat16 g_Wvh[DIM * DIM], g_Wvl[DIM * DIM];
__device__ __nv_bfloat16 g_Woh[DIM * DIM], g_Wol[DIM * DIM];
__device__ __nv_bfloat16 g_Qh[BH * SEQ * HDIM], g_Ql[BH * SEQ * HDIM];   // [bh][s][hd]
__device__ __nv_bfloat16 g_Kh[BH * SEQ * HDIM], g_Kl[BH * SEQ * HDIM];   // [bh][s][hd]
__device__ __nv_bfloat16 g_Vth[BH * HDIM * SEQ], g_Vtl[BH * HDIM * SEQ]; // [bh][hd][s]
__device__ float         g_S[(size_t)BH * SEQ * SEQ];                    // fp32 scores
__device__ __nv_bfloat16 g_Ph[(size_t)BH * SEQ * SEQ], g_Pl[(size_t)BH * SEQ * SEQ];
__device__ __nv_bfloat16 g_Ah[(size_t)MROWS * DIM], g_Al[(size_t)MROWS * DIM];

// ---------------- helpers ----------------
__device__ __forceinline__ uint32_t smem_u32(const void* p) {
    uint32_t a;
    asm("{ .reg .u64 t; cvta.to.shared.u64 t, %1; cvt.u32.u64 %0, t; }" : "=r"(a) : "l"(p));
    return a;
}
__device__ __forceinline__ void cp16(uint32_t s, const void* g) {
    asm volatile("cp.async.cg.shared.global [%0], [%1], 16;" :: "r"(s), "l"(g));
}
__device__ __forceinline__ void mma_bf16(float* d, const uint32_t* a, const uint32_t* b) {
    asm volatile(
        "mma.sync.aligned.m16n8k16.row.col.f32.bf16.bf16.f32 "
        "{%0,%1,%2,%3}, {%4,%5,%6,%7}, {%8,%9}, {%0,%1,%2,%3};"
        : "+f"(d[0]), "+f"(d[1]), "+f"(d[2]), "+f"(d[3])
        : "r"(a[0]), "r"(a[1]), "r"(a[2]), "r"(a[3]), "r"(b[0]), "r"(b[1]));
}

// ---------------- split conversion kernels ----------------
__global__ __launch_bounds__(256) void split_kernel(const float* __restrict__ in,
                                                    __nv_bfloat16* __restrict__ h,
                                                    __nv_bfloat16* __restrict__ l, int n) {
    int i = blockIdx.x * 256 + threadIdx.x;
    if (i < n) {
        float v = in[i];
        __nv_bfloat16 hi = __float2bfloat16(v);
        h[i] = hi;
        l[i] = __float2bfloat16(v - __bfloat162float(hi));
    }
}

__global__ __launch_bounds__(256) void wsplit_kernel(const float* __restrict__ W,
                                                     __nv_bfloat16* __restrict__ th,
                                                     __nv_bfloat16* __restrict__ tl) {
    __shared__ float t[32][33];
    int n0 = blockIdx.x * 32, k0 = blockIdx.y * 32;
    int tx = threadIdx.x & 31, ty = threadIdx.x >> 5;
#pragma unroll
    for (int r = ty; r < 32; r += 8)
        t[r][tx] = W[(size_t)(k0 + r) * DIM + n0 + tx];
    __syncthreads();
#pragma unroll
    for (int r = ty; r < 32; r += 8) {
        float v = t[tx][r];
        __nv_bfloat16 hi = __float2bfloat16(v);
        size_t idx = (size_t)(n0 + r) * DIM + k0 + tx;
        th[idx] = hi;
        tl[idx] = __float2bfloat16(v - __bfloat162float(hi));
    }
}

// ---------------- mma.sync split-bf16 GEMM: 512 threads, 16 warps (4M x 4N) ----------
// CTA tile 128 x TN, warp tile 32 x (TN/4), Kc = 32 double-buffered cp.async.
// modes: 0 Q/K head-split hi/lo, 1 V transposed hi/lo, 2 fp32 out (+bias),
//        3 fp32 scores (batched), 4 merged-head hi/lo (batched)
template <int TN>
__global__ __launch_bounds__(512, 1) void gemm_kernel(
    const __nv_bfloat16* __restrict__ Ah, const __nv_bfloat16* __restrict__ Al,
    long strideA, long bStrideA,
    const __nv_bfloat16* __restrict__ Bh, const __nv_bfloat16* __restrict__ Bl,
    long strideB, long bStrideB,
    const float* __restrict__ bias, float scale, int Ktot, int mode,
    __nv_bfloat16* __restrict__ outH, __nv_bfloat16* __restrict__ outL,
    float* __restrict__ outF)
{
    extern __shared__ char smem[];
    constexpr int WN  = TN / 4;      // warp N extent (32 or 16)
    constexpr int NT  = WN / 8;      // n8 tiles per warp (4 or 2)
    constexpr int ROWB = 80;         // 32 bf16 + 16B pad
    constexpr int A_H = 0;
    constexpr int A_L = 128 * ROWB;
    constexpr int B_H = 2 * 128 * ROWB;
    constexpr int B_L = 2 * 128 * ROWB + TN * ROWB;
    constexpr int STAGE = 2 * 128 * ROWB + 2 * TN * ROWB;

    const int tid = threadIdx.x;
    const int w = tid >> 5, lane = tid & 31;
    const int g = lane >> 2, t = lane & 3;
    const int wm = w & 3, wn = w >> 2;     // 4 x 4 warps
    const int z = blockIdx.z;
    Ah += (size_t)z * bStrideA;  Al += (size_t)z * bStrideA;
    Bh += (size_t)z * bStrideB;  Bl += (size_t)z * bStrideB;

    const int m0 = blockIdx.y * 128, n0 = blockIdx.x * TN;
    const int nch = Ktot >> 5;
    const uint32_t sb = smem_u32(smem);

    float acc[2][NT][4];
#pragma unroll
    for (int i = 0; i < 2; i++)
#pragma unroll
        for (int j = 0; j < NT; j++)
#pragma unroll
            for (int k = 0; k < 4; k++) acc[i][j][k] = 0.f;

    auto stage_load = [&](int buf, int c) {
        const int k0 = c << 5;
        const uint32_t so = sb + buf * STAGE;
#pragma unroll
        for (int i = tid; i < 512; i += 512) {
            int r = i >> 2, cc = i & 3;
            uint32_t off = r * ROWB + cc * 16;
            cp16(so + A_H + off, Ah + (size_t)(m0 + r) * strideA + k0 + cc * 8);
            cp16(so + A_L + off, Al + (size_t)(m0 + r) * strideA + k0 + cc * 8);
        }
#pragma unroll
        for (int i = tid; i < TN * 4; i += 512) {
            int r = i >> 2, cc = i & 3;
            uint32_t off = r * ROWB + cc * 16;
            cp16(so + B_H + off, Bh + (size_t)(n0 + r) * strideB + k0 + cc * 8);
            cp16(so + B_L + off, Bl + (size_t)(n0 + r) * strideB + k0 + cc * 8);
        }
        asm volatile("cp.async.commit_group;");
    };

    stage_load(0, 0);
    for (int c = 0; c < nch; c++) {
        const int buf = c & 1;
        if (c + 1 < nch) {
            stage_load(buf ^ 1, c + 1);
            asm volatile("cp.async.wait_group 1;");
        } else {
            asm volatile("cp.async.wait_group 0;");
        }
        __syncthreads();

        const char* s = smem + buf * STAGE;
#pragma unroll
        for (int ks = 0; ks < 2; ks++) {
            const int kb = ks * 32 + t * 4;
            uint32_t ah[2][4], al[2][4], bh[NT][2], bl[NT][2];
#pragma unroll
            for (int mt = 0; mt < 2; mt++) {
                const char* p = s + (wm * 32 + mt * 16 + g) * ROWB + kb;
                ah[mt][0] = *(const uint32_t*)(p + A_H);
                ah[mt][1] = *(const uint32_t*)(p + A_H + 8 * ROWB);
                ah[mt][2] = *(const uint32_t*)(p + A_H + 16);
                ah[mt][3] = *(const uint32_t*)(p + A_H + 8 * ROWB + 16);
                al[mt][0] = *(const uint32_t*)(p + A_L);
                al[mt][1] = *(const uint32_t*)(p + A_L + 8 * ROWB);
                al[mt][2] = *(const uint32_t*)(p + A_L + 16);
                al[mt][3] = *(const uint32_t*)(p + A_L + 8 * ROWB + 16);
            }
#pragma unroll
            for (int nt = 0; nt < NT; nt++) {
                const char* p = s + (wn * WN + nt * 8 + g) * ROWB + kb;
                bh[nt][0] = *(const uint32_t*)(p + B_H);
                bh[nt][1] = *(const uint32_t*)(p + B_H + 16);
                bl[nt][0] = *(const uint32_t*)(p + B_L);
                bl[nt][1] = *(const uint32_t*)(p + B_L + 16);
            }
#pragma unroll
            for (int mt = 0; mt < 2; mt++)
#pragma unroll
                for (int nt = 0; nt < NT; nt++) {
                    mma_bf16(acc[mt][nt], ah[mt], bh[nt]);
                    mma_bf16(acc[mt][nt], ah[mt], bl[nt]);
                    mma_bf16(acc[mt][nt], al[mt], bh[nt]);
                }
        }
        __syncthreads();
    }

    // ---------------- epilogue ----------------
#pragma unroll
    for (int mt = 0; mt < 2; mt++)
#pragma unroll
        for (int nt = 0; nt < NT; nt++)
#pragma unroll
            for (int p = 0; p < 2; p++) {
                int row = m0 + wm * 32 + mt * 16 + g + 8 * p;
                int col = n0 + wn * WN + nt * 8 + 2 * t;
                float v0 = acc[mt][nt][2 * p + 0];
                float v1 = acc[mt][nt][2 * p + 1];
                if (mode == 0 || mode == 1) {
                    int b = row >> 11, sq = row & (SEQ - 1);
                    v0 = (v0 + bias[col]) * scale;
                    v1 = (v1 + bias[col + 1]) * scale;
#pragma unroll
                    for (int e = 0; e < 2; e++) {
                        int cc = col + e;
                        float v = e ? v1 : v0;
                        int h = cc >> 6, hd = cc & (HDIM - 1);
                        __nv_bfloat16 hi = __float2bfloat16(v);
                        __nv_bfloat16 lo = __float2bfloat16(v - __bfloat162float(hi));
                        size_t idx = (mode == 0)
                            ? ((((size_t)b * NH + h) * SEQ + sq) * HDIM + hd)
                            : ((((size_t)b * NH + h) * HDIM + hd) * SEQ + sq);
                        outH[idx] = hi;
                        outL[idx] = lo;
                    }
                } else if (mode == 2) {
                    *(float2*)(outF + (size_t)row * DIM + col)
                        = make_float2(v0 + bias[col], v1 + bias[col + 1]);
                } else if (mode == 3) {
                    *(float2*)(outF + (size_t)z * SEQ * SEQ + (size_t)row * SEQ + col)
                        = make_float2(v0, v1);
                } else {  // mode 4
                    int b = z >> 4, h = z & (NH - 1);
                    size_t base = ((size_t)b * SEQ + row) * DIM + h * HDIM + col;
#pragma unroll
                    for (int e = 0; e < 2; e++) {
                        float v = e ? v1 : v0;
                        __nv_bfloat16 hi = __float2bfloat16(v);
                        outH[base + e] = hi;
                        outL[base + e] = __float2bfloat16(v - __bfloat162float(hi));
                    }
                }
            }
}

// ---------------- softmax (fp32 in, bf16 hi/lo out) ----------------
__global__ __launch_bounds__(256) void softmax_kernel() {
    const float* p = g_S + (size_t)blockIdx.x * SEQ;
    __nv_bfloat16* ph = g_Ph + (size_t)blockIdx.x * SEQ;
    __nv_bfloat16* pl = g_Pl + (size_t)blockIdx.x * SEQ;
    int tid = threadIdx.x, wid = tid >> 5, lid = tid & 31;
    __shared__ float sred[8];

    float v[8];
    float mx = -1e30f;
#pragma unroll
    for (int i = 0; i < 8; i++) { v[i] = p[tid + i * 256]; mx = fmaxf(mx, v[i]); }
#pragma unroll
    for (int o = 16; o > 0; o >>= 1) mx = fmaxf(mx, __shfl_xor_sync(0xffffffffu, mx, o));
    if (lid == 0) sred[wid] = mx;
    __syncthreads();
    if (wid == 0) {
        float t2 = sred[lid & 7];
#pragma unroll
        for (int o = 4; o > 0; o >>= 1) t2 = fmaxf(t2, __shfl_xor_sync(0xffffffffu, t2, o));
        if (lid == 0) sred[0] = t2;
    }
    __syncthreads();
    mx = sred[0];
    __syncthreads();
    float sum = 0.f;
#pragma unroll
    for (int i = 0; i < 8; i++) { v[i] = __expf(v[i] - mx); sum += v[i]; }
#pragma unroll
    for (int o = 16; o > 0; o >>= 1) sum += __shfl_xor_sync(0xffffffffu, sum, o);
    if (lid == 0) sred[wid] = sum;
    __syncthreads();
    if (wid == 0) {
        float t2 = sred[lid & 7];
#pragma unroll
        for (int o = 4; o > 0; o >>= 1) t2 += __shfl_xor_sync(0xffffffffu, t2, o);
        if (lid == 0) sred[0] = t2;
    }
    __syncthreads();
    float inv = 1.0f / sred[0];
#pragma unroll
    for (int i = 0; i < 8; i++) {
        float w = v[i] * inv;
        __nv_bfloat16 hi = __float2bfloat16(w);
        ph[tid + i * 256] = hi;
        pl[tid + i * 256] = __float2bfloat16(w - __bfloat162float(hi));
    }
}

// ---------------- host ----------------
static void* sym(const void* s) { void* p; cudaGetSymbolAddress(&p, s); return p; }

extern "C" void kernel_launch(void* const* d_in, const int* in_sizes, int n_in,
                              void* d_out, int out_size)
{
    const float* x  = (const float*)d_in[0];
    const float* Wq = (const float*)d_in[1];
    const float* bq = (const float*)d_in[2];
    const float* Wk = (const float*)d_in[3];
    const float* bk = (const float*)d_in[4];
    const float* Wv = (const float*)d_in[5];
    const float* bv = (const float*)d_in[6];
    const float* Wo = (const float*)d_in[7];
    const float* bo = (const float*)d_in[8];
    float* out = (float*)d_out;

    constexpr int SMEM128 = 2 * (2 * 128 * 80 + 2 * 128 * 80);  // 81920
    constexpr int SMEM64  = 2 * (2 * 128 * 80 + 2 * 64 * 80);   // 61440
    cudaFuncSetAttribute(gemm_kernel<128>, cudaFuncAttributeMaxDynamicSharedMemorySize, SMEM128);
    cudaFuncSetAttribute(gemm_kernel<64>,  cudaFuncAttributeMaxDynamicSharedMemorySize, SMEM64);

    __nv_bfloat16 *xh = (__nv_bfloat16*)sym(g_xh), *xl = (__nv_bfloat16*)sym(g_xl);
    __nv_bfloat16 *wqh = (__nv_bfloat16*)sym(g_Wqh), *wql = (__nv_bfloat16*)sym(g_Wql);
    __nv_bfloat16 *wkh = (__nv_bfloat16*)sym(g_Wkh), *wkl = (__nv_bfloat16*)sym(g_Wkl);
    __nv_bfloat16 *wvh = (__nv_bfloat16*)sym(g_Wvh), *wvl = (__nv_bfloat16*)sym(g_Wvl);
    __nv_bfloat16 *woh = (__nv_bfloat16*)sym(g_Woh), *wol = (__nv_bfloat16*)sym(g_Wol);
    __nv_bfloat16 *qh = (__nv_bfloat16*)sym(g_Qh), *ql = (__nv_bfloat16*)sym(g_Ql);
    __nv_bfloat16 *kh = (__nv_bfloat16*)sym(g_Kh), *kl = (__nv_bfloat16*)sym(g_Kl);
    __nv_bfloat16 *vth = (__nv_bfloat16*)sym(g_Vth), *vtl = (__nv_bfloat16*)sym(g_Vtl);
    __nv_bfloat16 *pwh = (__nv_bfloat16*)sym(g_Ph), *pwl = (__nv_bfloat16*)sym(g_Pl);
    __nv_bfloat16 *ah = (__nv_bfloat16*)sym(g_Ah), *al = (__nv_bfloat16*)sym(g_Al);
    float* Sf = (float*)sym(g_S);

    split_kernel<<<(MROWS * DIM + 255) / 256, 256>>>(x, xh, xl, MROWS * DIM);
    dim3 wg(DIM / 32, DIM / 32);
    wsplit_kernel<<<wg, 256>>>(Wq, wqh, wql);
    wsplit_kernel<<<wg, 256>>>(Wk, wkh, wkl);
    wsplit_kernel<<<wg, 256>>>(Wv, wvh, wvl);
    wsplit_kernel<<<wg, 256>>>(Wo, woh, wol);

    dim3 blk(512);
    dim3 gproj(DIM / 128, MROWS / 128, 1);

    gemm_kernel<128><<<gproj, blk, SMEM128>>>(xh, xl, DIM, 0, wqh, wql, DIM, 0,
        bq, 0.125f, DIM, 0, qh, ql, nullptr);
    gemm_kernel<128><<<gproj, blk, SMEM128>>>(xh, xl, DIM, 0, wkh, wkl, DIM, 0,
        bk, 1.0f, DIM, 0, kh, kl, nullptr);
    gemm_kernel<128><<<gproj, blk, SMEM128>>>(xh, xl, DIM, 0, wvh, wvl, DIM, 0,
        bv, 1.0f, DIM, 1, vth, vtl, nullptr);

    // scores = Qs @ K^T  (per head, K=64)
    gemm_kernel<128><<<dim3(SEQ / 128, SEQ / 128, BH), blk, SMEM128>>>(
        qh, ql, HDIM, (long)SEQ * HDIM, kh, kl, HDIM, (long)SEQ * HDIM,
        nullptr, 1.0f, HDIM, 3, nullptr, nullptr, Sf);

    softmax_kernel<<<BH * SEQ, 256>>>();

    // attn = P @ V^T  (N = 64)
    gemm_kernel<64><<<dim3(1, SEQ / 128, BH), blk, SMEM64>>>(
        pwh, pwl, SEQ, (long)SEQ * SEQ, vth, vtl, SEQ, (long)HDIM * SEQ,
        nullptr, 1.0f, SEQ, 4, ah, al, nullptr);

    gemm_kernel<128><<<gproj, blk, SMEM128>>>(ah, al, DIM, 0, woh, wol, DIM, 0,
        bo, 1.0f, DIM, 2, nullptr, nullptr, out);
}

// round 8
// speedup vs baseline: 3.8434x; 1.1616x over previous
#include <cuda_runtime.h>
#include <cuda_bf16.h>
#include <math.h>
#include <stdint.h>

#define BH    32
#define SEQ   2048
#define DIM   1024
#define NH    16
#define HDIM  64
#define MROWS 4096

// ---------------- device scratch ----------------
__device__ __nv_bfloat16 g_xh[MROWS * DIM], g_xl[MROWS * DIM];
__device__ __nv_bfloat16 g_Wqh[DIM * DIM], g_Wql[DIM * DIM];
__device__ __nv_bfloat16 g_Wkh[DIM * DIM], g_Wkl[DIM * DIM];
__device__ __nv_bfloat16 g_Wvh[DIM * DIM], g_Wvl[DIM * DIM];
__device__ __nv_bfloat16 g_Woh[DIM * DIM], g_Wol[DIM * DIM];
__device__ __nv_bfloat16 g_Qh[BH * SEQ * HDIM], g_Ql[BH * SEQ * HDIM];   // [bh][s][hd]
__device__ __nv_bfloat16 g_Kh[BH * SEQ * HDIM], g_Kl[BH * SEQ * HDIM];   // [bh][s][hd]
__device__ __nv_bfloat16 g_Vth[BH * HDIM * SEQ], g_Vtl[BH * HDIM * SEQ]; // [bh][hd][s]
__device__ __nv_bfloat16 g_Ph[(size_t)BH * SEQ * SEQ], g_Pl[(size_t)BH * SEQ * SEQ];
__device__ float         g_rowsum[BH * SEQ];
__device__ __nv_bfloat16 g_Ah[(size_t)MROWS * DIM], g_Al[(size_t)MROWS * DIM];

// ---------------- helpers ----------------
__device__ __forceinline__ uint32_t smem_u32(const void* p) {
    uint32_t a;
    asm("{ .reg .u64 t; cvta.to.shared.u64 t, %1; cvt.u32.u64 %0, t; }" : "=r"(a) : "l"(p));
    return a;
}
__device__ __forceinline__ void cp16(uint32_t s, const void* g) {
    asm volatile("cp.async.cg.shared.global [%0], [%1], 16;" :: "r"(s), "l"(g));
}
__device__ __forceinline__ void mma_bf16(float* d, const uint32_t* a, const uint32_t* b) {
    asm volatile(
        "mma.sync.aligned.m16n8k16.row.col.f32.bf16.bf16.f32 "
        "{%0,%1,%2,%3}, {%4,%5,%6,%7}, {%8,%9}, {%0,%1,%2,%3};"
        : "+f"(d[0]), "+f"(d[1]), "+f"(d[2]), "+f"(d[3])
        : "r"(a[0]), "r"(a[1]), "r"(a[2]), "r"(a[3]), "r"(b[0]), "r"(b[1]));
}
__device__ __forceinline__ void split2(float v0, float v1, uint32_t& h, uint32_t& l) {
    __nv_bfloat16 h0 = __float2bfloat16(v0), h1 = __float2bfloat16(v1);
    h = ((uint32_t)__bfloat16_as_ushort(h1) << 16) | __bfloat16_as_ushort(h0);
    __nv_bfloat16 l0 = __float2bfloat16(v0 - __bfloat162float(h0));
    __nv_bfloat16 l1 = __float2bfloat16(v1 - __bfloat162float(h1));
    l = ((uint32_t)__bfloat16_as_ushort(l1) << 16) | __bfloat16_as_ushort(l0);
}

// ---------------- split conversion kernels ----------------
__global__ __launch_bounds__(256) void split_kernel(const float* __restrict__ in,
                                                    __nv_bfloat16* __restrict__ h,
                                                    __nv_bfloat16* __restrict__ l, int n) {
    int i = blockIdx.x * 256 + threadIdx.x;
    if (i < n) {
        float v = in[i];
        __nv_bfloat16 hi = __float2bfloat16(v);
        h[i] = hi;
        l[i] = __float2bfloat16(v - __bfloat162float(hi));
    }
}

__global__ __launch_bounds__(256) void wsplit_kernel(const float* __restrict__ W,
                                                     __nv_bfloat16* __restrict__ th,
                                                     __nv_bfloat16* __restrict__ tl) {
    __shared__ float t[32][33];
    int n0 = blockIdx.x * 32, k0 = blockIdx.y * 32;
    int tx = threadIdx.x & 31, ty = threadIdx.x >> 5;
#pragma unroll
    for (int r = ty; r < 32; r += 8)
        t[r][tx] = W[(size_t)(k0 + r) * DIM + n0 + tx];
    __syncthreads();
#pragma unroll
    for (int r = ty; r < 32; r += 8) {
        float v = t[tx][r];
        __nv_bfloat16 hi = __float2bfloat16(v);
        size_t idx = (size_t)(n0 + r) * DIM + k0 + tx;
        th[idx] = hi;
        tl[idx] = __float2bfloat16(v - __bfloat162float(hi));
    }
}

// ---------------- mma.sync split-bf16 GEMM (R3 config: 256 thr, 8 warps 4Mx2N) -----
// modes: 0 Q/K head-split hi/lo, 1 V transposed hi/lo, 2 fp32 out (+bias),
//        3 exp(scores) -> P hi/lo + atomic row sums (batched),
//        4 merged-head hi/lo scaled by 1/rowsum (batched)
template <int TN>
__global__ __launch_bounds__(256, 1) void gemm_kernel(
    const __nv_bfloat16* __restrict__ Ah, const __nv_bfloat16* __restrict__ Al,
    long strideA, long bStrideA,
    const __nv_bfloat16* __restrict__ Bh, const __nv_bfloat16* __restrict__ Bl,
    long strideB, long bStrideB,
    const float* __restrict__ bias, float scale, int Ktot, int mode,
    __nv_bfloat16* __restrict__ outH, __nv_bfloat16* __restrict__ outL,
    float* __restrict__ outF, float* __restrict__ rowsum)
{
    extern __shared__ char smem[];
    constexpr int WN  = TN / 2;
    constexpr int NT  = WN / 8;
    constexpr int ROWB = 80;
    constexpr int A_H = 0;
    constexpr int A_L = 128 * ROWB;
    constexpr int B_H = 2 * 128 * ROWB;
    constexpr int B_L = 2 * 128 * ROWB + TN * ROWB;
    constexpr int STAGE = 2 * 128 * ROWB + 2 * TN * ROWB;

    const int tid = threadIdx.x;
    const int w = tid >> 5, lane = tid & 31;
    const int g = lane >> 2, t = lane & 3;
    const int wm = w & 3, wn = w >> 2;
    const int z = blockIdx.z;
    Ah += (size_t)z * bStrideA;  Al += (size_t)z * bStrideA;
    Bh += (size_t)z * bStrideB;  Bl += (size_t)z * bStrideB;

    const int m0 = blockIdx.y * 128, n0 = blockIdx.x * TN;
    const int nch = Ktot >> 5;
    const uint32_t sb = smem_u32(smem);

    float acc[2][NT][4];
#pragma unroll
    for (int i = 0; i < 2; i++)
#pragma unroll
        for (int j = 0; j < NT; j++)
#pragma unroll
            for (int k = 0; k < 4; k++) acc[i][j][k] = 0.f;

    auto stage_load = [&](int buf, int c) {
        const int k0 = c << 5;
        const uint32_t so = sb + buf * STAGE;
#pragma unroll
        for (int i = tid; i < 512; i += 256) {
            int r = i >> 2, cc = i & 3;
            uint32_t off = r * ROWB + cc * 16;
            cp16(so + A_H + off, Ah + (size_t)(m0 + r) * strideA + k0 + cc * 8);
            cp16(so + A_L + off, Al + (size_t)(m0 + r) * strideA + k0 + cc * 8);
        }
#pragma unroll
        for (int i = tid; i < TN * 4; i += 256) {
            int r = i >> 2, cc = i & 3;
            uint32_t off = r * ROWB + cc * 16;
            cp16(so + B_H + off, Bh + (size_t)(n0 + r) * strideB + k0 + cc * 8);
            cp16(so + B_L + off, Bl + (size_t)(n0 + r) * strideB + k0 + cc * 8);
        }
        asm volatile("cp.async.commit_group;");
    };

    stage_load(0, 0);
    for (int c = 0; c < nch; c++) {
        const int buf = c & 1;
        if (c + 1 < nch) {
            stage_load(buf ^ 1, c + 1);
            asm volatile("cp.async.wait_group 1;");
        } else {
            asm volatile("cp.async.wait_group 0;");
        }
        __syncthreads();

        const char* s = smem + buf * STAGE;
#pragma unroll
        for (int ks = 0; ks < 2; ks++) {
            const int kb = ks * 32 + t * 4;
            uint32_t ah[2][4], al[2][4], bh[NT][2], bl[NT][2];
#pragma unroll
            for (int mt = 0; mt < 2; mt++) {
                const char* p = s + (wm * 32 + mt * 16 + g) * ROWB + kb;
                ah[mt][0] = *(const uint32_t*)(p + A_H);
                ah[mt][1] = *(const uint32_t*)(p + A_H + 8 * ROWB);
                ah[mt][2] = *(const uint32_t*)(p + A_H + 16);
                ah[mt][3] = *(const uint32_t*)(p + A_H + 8 * ROWB + 16);
                al[mt][0] = *(const uint32_t*)(p + A_L);
                al[mt][1] = *(const uint32_t*)(p + A_L + 8 * ROWB);
                al[mt][2] = *(const uint32_t*)(p + A_L + 16);
                al[mt][3] = *(const uint32_t*)(p + A_L + 8 * ROWB + 16);
            }
#pragma unroll
            for (int nt = 0; nt < NT; nt++) {
                const char* p = s + (wn * WN + nt * 8 + g) * ROWB + kb;
                bh[nt][0] = *(const uint32_t*)(p + B_H);
                bh[nt][1] = *(const uint32_t*)(p + B_H + 16);
                bl[nt][0] = *(const uint32_t*)(p + B_L);
                bl[nt][1] = *(const uint32_t*)(p + B_L + 16);
            }
#pragma unroll
            for (int mt = 0; mt < 2; mt++)
#pragma unroll
                for (int nt = 0; nt < NT; nt++) {
                    mma_bf16(acc[mt][nt], ah[mt], bh[nt]);
                    mma_bf16(acc[mt][nt], ah[mt], bl[nt]);
                    mma_bf16(acc[mt][nt], al[mt], bh[nt]);
                }
        }
        __syncthreads();
    }

    // ---------------- epilogue ----------------
    if (mode == 3) {
        // exp in-place, accumulate per-row partial sums, write P hi/lo, atomic rowsum
        float rs[2][2] = {};
#pragma unroll
        for (int mt = 0; mt < 2; mt++)
#pragma unroll
            for (int nt = 0; nt < NT; nt++)
#pragma unroll
                for (int p = 0; p < 2; p++) {
                    float e0 = __expf(acc[mt][nt][2 * p + 0]);
                    float e1 = __expf(acc[mt][nt][2 * p + 1]);
                    acc[mt][nt][2 * p + 0] = e0;
                    acc[mt][nt][2 * p + 1] = e1;
                    rs[mt][p] += e0 + e1;
                }
#pragma unroll
        for (int mt = 0; mt < 2; mt++)
#pragma unroll
            for (int p = 0; p < 2; p++) {
                int row = m0 + wm * 32 + mt * 16 + g + 8 * p;
#pragma unroll
                for (int nt = 0; nt < NT; nt++) {
                    int col = n0 + wn * WN + nt * 8 + 2 * t;
                    size_t ofs = (size_t)z * SEQ * SEQ + (size_t)row * SEQ + col;
                    uint32_t hh, ll;
                    split2(acc[mt][nt][2 * p + 0], acc[mt][nt][2 * p + 1], hh, ll);
                    *(uint32_t*)(outH + ofs) = hh;
                    *(uint32_t*)(outL + ofs) = ll;
                }
                float s2 = rs[mt][p];
                s2 += __shfl_xor_sync(0xffffffffu, s2, 1);
                s2 += __shfl_xor_sync(0xffffffffu, s2, 2);
                if (t == 0) atomicAdd(&rowsum[z * SEQ + row], s2);
            }
        return;
    }

#pragma unroll
    for (int mt = 0; mt < 2; mt++)
#pragma unroll
        for (int nt = 0; nt < NT; nt++)
#pragma unroll
            for (int p = 0; p < 2; p++) {
                int row = m0 + wm * 32 + mt * 16 + g + 8 * p;
                int col = n0 + wn * WN + nt * 8 + 2 * t;
                float v0 = acc[mt][nt][2 * p + 0];
                float v1 = acc[mt][nt][2 * p + 1];
                if (mode == 0 || mode == 1) {
                    int b = row >> 11, sq = row & (SEQ - 1);
                    v0 = (v0 + bias[col]) * scale;
                    v1 = (v1 + bias[col + 1]) * scale;
#pragma unroll
                    for (int e = 0; e < 2; e++) {
                        int cc = col + e;
                        float v = e ? v1 : v0;
                        int h = cc >> 6, hd = cc & (HDIM - 1);
                        __nv_bfloat16 hi = __float2bfloat16(v);
                        __nv_bfloat16 lo = __float2bfloat16(v - __bfloat162float(hi));
                        size_t idx = (mode == 0)
                            ? ((((size_t)b * NH + h) * SEQ + sq) * HDIM + hd)
                            : ((((size_t)b * NH + h) * HDIM + hd) * SEQ + sq);
                        outH[idx] = hi;
                        outL[idx] = lo;
                    }
                } else if (mode == 2) {
                    *(float2*)(outF + (size_t)row * DIM + col)
                        = make_float2(v0 + bias[col], v1 + bias[col + 1]);
                } else {  // mode 4: merged-head, normalize by rowsum
                    float inv = 1.0f / rowsum[z * SEQ + row];
                    v0 *= inv;
                    v1 *= inv;
                    int b = z >> 4, h = z & (NH - 1);
                    size_t base = ((size_t)b * SEQ + row) * DIM + h * HDIM + col;
                    uint32_t hh, ll;
                    split2(v0, v1, hh, ll);
                    *(uint32_t*)(outH + base) = hh;
                    *(uint32_t*)(outL + base) = ll;
                }
            }
}

// ---------------- host ----------------
static void* sym(const void* s) { void* p; cudaGetSymbolAddress(&p, s); return p; }

extern "C" void kernel_launch(void* const* d_in, const int* in_sizes, int n_in,
                              void* d_out, int out_size)
{
    const float* x  = (const float*)d_in[0];
    const float* Wq = (const float*)d_in[1];
    const float* bq = (const float*)d_in[2];
    const float* Wk = (const float*)d_in[3];
    const float* bk = (const float*)d_in[4];
    const float* Wv = (const float*)d_in[5];
    const float* bv = (const float*)d_in[6];
    const float* Wo = (const float*)d_in[7];
    const float* bo = (const float*)d_in[8];
    float* out = (float*)d_out;

    constexpr int SMEM128 = 2 * (2 * 128 * 80 + 2 * 128 * 80);  // 81920
    constexpr int SMEM64  = 2 * (2 * 128 * 80 + 2 * 64 * 80);   // 61440
    cudaFuncSetAttribute(gemm_kernel<128>, cudaFuncAttributeMaxDynamicSharedMemorySize, SMEM128);
    cudaFuncSetAttribute(gemm_kernel<64>,  cudaFuncAttributeMaxDynamicSharedMemorySize, SMEM64);

    __nv_bfloat16 *xh = (__nv_bfloat16*)sym(g_xh), *xl = (__nv_bfloat16*)sym(g_xl);
    __nv_bfloat16 *wqh = (__nv_bfloat16*)sym(g_Wqh), *wql = (__nv_bfloat16*)sym(g_Wql);
    __nv_bfloat16 *wkh = (__nv_bfloat16*)sym(g_Wkh), *wkl = (__nv_bfloat16*)sym(g_Wkl);
    __nv_bfloat16 *wvh = (__nv_bfloat16*)sym(g_Wvh), *wvl = (__nv_bfloat16*)sym(g_Wvl);
    __nv_bfloat16 *woh = (__nv_bfloat16*)sym(g_Woh), *wol = (__nv_bfloat16*)sym(g_Wol);
    __nv_bfloat16 *qh = (__nv_bfloat16*)sym(g_Qh), *ql = (__nv_bfloat16*)sym(g_Ql);
    __nv_bfloat16 *kh = (__nv_bfloat16*)sym(g_Kh), *kl = (__nv_bfloat16*)sym(g_Kl);
    __nv_bfloat16 *vth = (__nv_bfloat16*)sym(g_Vth), *vtl = (__nv_bfloat16*)sym(g_Vtl);
    __nv_bfloat16 *pwh = (__nv_bfloat16*)sym(g_Ph), *pwl = (__nv_bfloat16*)sym(g_Pl);
    __nv_bfloat16 *ah = (__nv_bfloat16*)sym(g_Ah), *al = (__nv_bfloat16*)sym(g_Al);
    float* rsum = (float*)sym(g_rowsum);

    // zero row sums (re-done every replay for determinism)
    cudaMemsetAsync(rsum, 0, BH * SEQ * sizeof(float), 0);

    split_kernel<<<(MROWS * DIM + 255) / 256, 256>>>(x, xh, xl, MROWS * DIM);
    dim3 wg(DIM / 32, DIM / 32);
    wsplit_kernel<<<wg, 256>>>(Wq, wqh, wql);
    wsplit_kernel<<<wg, 256>>>(Wk, wkh, wkl);
    wsplit_kernel<<<wg, 256>>>(Wv, wvh, wvl);
    wsplit_kernel<<<wg, 256>>>(Wo, woh, wol);

    dim3 blk(256);
    dim3 gproj(DIM / 128, MROWS / 128, 1);

    gemm_kernel<128><<<gproj, blk, SMEM128>>>(xh, xl, DIM, 0, wqh, wql, DIM, 0,
        bq, 0.125f, DIM, 0, qh, ql, nullptr, nullptr);
    gemm_kernel<128><<<gproj, blk, SMEM128>>>(xh, xl, DIM, 0, wkh, wkl, DIM, 0,
        bk, 1.0f, DIM, 0, kh, kl, nullptr, nullptr);
    gemm_kernel<128><<<gproj, blk, SMEM128>>>(xh, xl, DIM, 0, wvh, wvl, DIM, 0,
        bv, 1.0f, DIM, 1, vth, vtl, nullptr, nullptr);

    // scores + exp + row sums: P = exp(Qs K^T), rowsum accumulated atomically
    gemm_kernel<128><<<dim3(SEQ / 128, SEQ / 128, BH), blk, SMEM128>>>(
        qh, ql, HDIM, (long)SEQ * HDIM, kh, kl, HDIM, (long)SEQ * HDIM,
        nullptr, 1.0f, HDIM, 3, pwh, pwl, nullptr, rsum);

    // attn = (P @ V^T) / rowsum
    gemm_kernel<64><<<dim3(1, SEQ / 128, BH), blk, SMEM64>>>(
        pwh, pwl, SEQ, (long)SEQ * SEQ, vth, vtl, SEQ, (long)HDIM * SEQ,
        nullptr, 1.0f, SEQ, 4, ah, al, nullptr, rsum);

    gemm_kernel<128><<<gproj, blk, SMEM128>>>(ah, al, DIM, 0, woh, wol, DIM, 0,
        bo, 1.0f, DIM, 2, nullptr, nullptr, out, nullptr);
}